// round 5
// baseline (speedup 1.0000x reference)
#include <cuda_runtime.h>
#include <cstdint>

#define NSTEPS 64
#define DD 16
#define THREADS 384
#define RPT 4
#define ROWS_PER_CTA (THREADS * RPT)          // 1536
#define WEIGHT_FLOATS (NSTEPS * DD * DD)
#define SMEM_BYTES (2 * WEIGHT_FLOATS * 4)    // 128 KB: W then V/64

typedef unsigned long long u64;

// ---- packed f32x2 helpers (sm_103a) ----
__device__ __forceinline__ u64 pack2(float lo, float hi) {
    u64 r;
    asm("mov.b64 %0, {%1, %2};" : "=l"(r) : "f"(lo), "f"(hi));
    return r;
}
__device__ __forceinline__ void unpack2(u64 v, float& lo, float& hi) {
    asm("mov.b64 {%0, %1}, %2;" : "=f"(lo), "=f"(hi) : "l"(v));
}
__device__ __forceinline__ u64 fma2(u64 a, u64 b, u64 c) {
    u64 d;
    asm("fma.rn.f32x2 %0, %1, %2, %3;" : "=l"(d) : "l"(a), "l"(b), "l"(c));
    return d;
}
__device__ __forceinline__ u64 mul2(u64 a, u64 b) {
    u64 d;
    asm("mul.rn.f32x2 %0, %1, %2;" : "=l"(d) : "l"(a), "l"(b));
    return d;
}
__device__ __forceinline__ float rcp_fast(float x) {
    float r;
    asm("rcp.approx.ftz.f32 %0, %1;" : "=f"(r) : "f"(x));
    return r;
}
__device__ __forceinline__ float ex2_fast(float x) {
    float r;
    asm("ex2.approx.ftz.f32 %0, %1;" : "=f"(r) : "f"(x));
    return r;
}

// A&S 7.1.26 erf constants
#define ERF_P   0.3275911f
#define ERF_A1  0.254829592f
#define ERF_A2 -0.284496736f
#define ERF_A3  1.421413741f
#define ERF_A4 -1.453152027f
#define ERF_A5  1.061405429f
#define INV_SQRT2 0.70710678118654752440f
#define NEG_LOG2E -1.44269504088896340736f

// gelu on a packed pair: returns (gelu(x), gelu(y)); erf via A&S 7.1.26
__device__ __forceinline__ u64 gelu2(u64 xy) {
    float x, y;
    unpack2(xy, x, y);
    float ax = fabsf(x) * INV_SQRT2;
    float ay = fabsf(y) * INV_SQRT2;
    float tx = rcp_fast(fmaf(ERF_P, ax, 1.0f));
    float ty = rcp_fast(fmaf(ERF_P, ay, 1.0f));
    float ex = ex2_fast(ax * ax * NEG_LOG2E);
    float ey = ex2_fast(ay * ay * NEG_LOG2E);
    u64 t2 = pack2(tx, ty);
    u64 e2 = pack2(ex, ey);
    // P = -(a5 t^5 + ... + a1 t) via negated coefs (packed Horner)
    u64 p = fma2(pack2(-ERF_A5, -ERF_A5), t2, pack2(-ERF_A4, -ERF_A4));
    p = fma2(p, t2, pack2(-ERF_A3, -ERF_A3));
    p = fma2(p, t2, pack2(-ERF_A2, -ERF_A2));
    p = fma2(p, t2, pack2(-ERF_A1, -ERF_A1));
    p = mul2(p, t2);
    u64 E2 = fma2(p, e2, pack2(1.0f, 1.0f));               // E = 1 - P(t)*e^{-z^2}
    u64 half2 = pack2(0.5f, 0.5f);
    u64 habs = mul2(xy & 0x7fffffff7fffffffULL, half2);     // 0.5*|x|
    u64 hx = mul2(xy, half2);                               // 0.5*x
    return fma2(habs, E2, hx);                              // 0.5x + 0.5|x|*E
}

__global__ __launch_bounds__(THREADS)
void resnet_steps_kernel(const float* __restrict__ x,
                         const float* __restrict__ W,
                         const float* __restrict__ V,
                         float* __restrict__ out,
                         long long batch)
{
    extern __shared__ float smem[];   // [0,16384): W ; [16384,32768): V * (1/64)
    const int tid = threadIdx.x;

    {
        const float4* Wg = reinterpret_cast<const float4*>(W);
        const float4* Vg = reinterpret_cast<const float4*>(V);
        float4* sW4 = reinterpret_cast<float4*>(smem);
        float4* sV4 = reinterpret_cast<float4*>(smem + WEIGHT_FLOATS);
        const float invn = 1.0f / (float)NSTEPS;
        for (int i = tid; i < WEIGHT_FLOATS / 4; i += THREADS) {
            sW4[i] = Wg[i];
            float4 v = Vg[i];
            v.x *= invn; v.y *= invn; v.z *= invn; v.w *= invn;
            sV4[i] = v;
        }
    }
    __syncthreads();

    const long long base_row = (long long)blockIdx.x * ROWS_PER_CTA + tid;

    u64 h[RPT][8];
    #pragma unroll
    for (int r = 0; r < RPT; r++) {
        const long long row = base_row + (long long)r * THREADS;
        if (row < batch) {
            const float4* xr = reinterpret_cast<const float4*>(x + row * DD);
            #pragma unroll
            for (int q = 0; q < 4; q++) {
                float4 t = xr[q];
                h[r][2 * q]     = pack2(t.x, t.y);
                h[r][2 * q + 1] = pack2(t.z, t.w);
            }
        } else {
            #pragma unroll
            for (int i = 0; i < 8; i++) h[r][i] = 0ULL;
        }
    }

    const ulonglong2* sW = reinterpret_cast<const ulonglong2*>(smem);
    const ulonglong2* sV = reinterpret_cast<const ulonglong2*>(smem + WEIGHT_FLOATS);

    #pragma unroll 1
    for (int s = 0; s < NSTEPS; s++) {
        const ulonglong2* Ws = sW + s * (DD * DD / 4);
        const ulonglong2* Vs = sV + s * (DD * DD / 4);

        // ---- g = h @ W_s ----
        u64 acc[RPT][8];
        #pragma unroll
        for (int r = 0; r < RPT; r++)
            #pragma unroll
            for (int i = 0; i < 8; i++) acc[r][i] = 0ULL;

        #pragma unroll 1
        for (int kp = 0; kp < 8; kp++) {
            float alo[RPT], ahi[RPT];
            #pragma unroll
            for (int r = 0; r < RPT; r++) unpack2(h[r][kp], alo[r], ahi[r]);

            // W row 2kp (4 ulonglong2 live)
            {
                ulonglong2 w0 = Ws[kp * 8 + 0];
                ulonglong2 w1 = Ws[kp * 8 + 1];
                ulonglong2 w2 = Ws[kp * 8 + 2];
                ulonglong2 w3 = Ws[kp * 8 + 3];
                #pragma unroll
                for (int r = 0; r < RPT; r++) {
                    const u64 ha = pack2(alo[r], alo[r]);
                    acc[r][0] = fma2(ha, w0.x, acc[r][0]);
                    acc[r][1] = fma2(ha, w0.y, acc[r][1]);
                    acc[r][2] = fma2(ha, w1.x, acc[r][2]);
                    acc[r][3] = fma2(ha, w1.y, acc[r][3]);
                    acc[r][4] = fma2(ha, w2.x, acc[r][4]);
                    acc[r][5] = fma2(ha, w2.y, acc[r][5]);
                    acc[r][6] = fma2(ha, w3.x, acc[r][6]);
                    acc[r][7] = fma2(ha, w3.y, acc[r][7]);
                }
            }
            // W row 2kp+1
            {
                ulonglong2 w4 = Ws[kp * 8 + 4];
                ulonglong2 w5 = Ws[kp * 8 + 5];
                ulonglong2 w6 = Ws[kp * 8 + 6];
                ulonglong2 w7 = Ws[kp * 8 + 7];
                #pragma unroll
                for (int r = 0; r < RPT; r++) {
                    const u64 hb = pack2(ahi[r], ahi[r]);
                    acc[r][0] = fma2(hb, w4.x, acc[r][0]);
                    acc[r][1] = fma2(hb, w4.y, acc[r][1]);
                    acc[r][2] = fma2(hb, w5.x, acc[r][2]);
                    acc[r][3] = fma2(hb, w5.y, acc[r][3]);
                    acc[r][4] = fma2(hb, w6.x, acc[r][4]);
                    acc[r][5] = fma2(hb, w6.y, acc[r][5]);
                    acc[r][6] = fma2(hb, w7.x, acc[r][6]);
                    acc[r][7] = fma2(hb, w7.y, acc[r][7]);
                }
            }
        }

        // ---- h += GELU(g) @ (V_s/64); fast packed A&S erf ----
        #pragma unroll 1
        for (int kp = 0; kp < 8; kp++) {
            float glo[RPT], ghi[RPT];
            #pragma unroll
            for (int r = 0; r < RPT; r++) {
                u64 g2 = gelu2(acc[r][kp]);
                unpack2(g2, glo[r], ghi[r]);
            }
            {
                ulonglong2 v0 = Vs[kp * 8 + 0];
                ulonglong2 v1 = Vs[kp * 8 + 1];
                ulonglong2 v2 = Vs[kp * 8 + 2];
                ulonglong2 v3 = Vs[kp * 8 + 3];
                #pragma unroll
                for (int r = 0; r < RPT; r++) {
                    const u64 ga = pack2(glo[r], glo[r]);
                    h[r][0] = fma2(ga, v0.x, h[r][0]);
                    h[r][1] = fma2(ga, v0.y, h[r][1]);
                    h[r][2] = fma2(ga, v1.x, h[r][2]);
                    h[r][3] = fma2(ga, v1.y, h[r][3]);
                    h[r][4] = fma2(ga, v2.x, h[r][4]);
                    h[r][5] = fma2(ga, v2.y, h[r][5]);
                    h[r][6] = fma2(ga, v3.x, h[r][6]);
                    h[r][7] = fma2(ga, v3.y, h[r][7]);
                }
            }
            {
                ulonglong2 v4 = Vs[kp * 8 + 4];
                ulonglong2 v5 = Vs[kp * 8 + 5];
                ulonglong2 v6 = Vs[kp * 8 + 6];
                ulonglong2 v7 = Vs[kp * 8 + 7];
                #pragma unroll
                for (int r = 0; r < RPT; r++) {
                    const u64 gb = pack2(ghi[r], ghi[r]);
                    h[r][0] = fma2(gb, v4.x, h[r][0]);
                    h[r][1] = fma2(gb, v4.y, h[r][1]);
                    h[r][2] = fma2(gb, v5.x, h[r][2]);
                    h[r][3] = fma2(gb, v5.y, h[r][3]);
                    h[r][4] = fma2(gb, v6.x, h[r][4]);
                    h[r][5] = fma2(gb, v6.y, h[r][5]);
                    h[r][6] = fma2(gb, v7.x, h[r][6]);
                    h[r][7] = fma2(gb, v7.y, h[r][7]);
                }
            }
        }
    }

    #pragma unroll
    for (int r = 0; r < RPT; r++) {
        const long long row = base_row + (long long)r * THREADS;
        if (row < batch) {
            float4* orow = reinterpret_cast<float4*>(out + row * DD);
            #pragma unroll
            for (int q = 0; q < 4; q++) {
                float4 t;
                unpack2(h[r][2 * q],     t.x, t.y);
                unpack2(h[r][2 * q + 1], t.z, t.w);
                orow[q] = t;
            }
        }
    }
}

extern "C" void kernel_launch(void* const* d_in, const int* in_sizes, int n_in,
                              void* d_out, int out_size) {
    const float* x = (const float*)d_in[0];
    const float* W = (const float*)d_in[1];
    const float* V = (const float*)d_in[2];
    float* out = (float*)d_out;

    static bool attr_set = false;
    if (!attr_set) {
        cudaFuncSetAttribute(resnet_steps_kernel,
                             cudaFuncAttributeMaxDynamicSharedMemorySize, SMEM_BYTES);
        attr_set = true;
    }

    const long long batch = (long long)in_sizes[0] / DD;   // 2^21
    const int grid = (int)((batch + ROWS_PER_CTA - 1) / ROWS_PER_CTA);
    resnet_steps_kernel<<<grid, THREADS, SMEM_BYTES>>>(x, W, V, out, batch);
}

// round 6
// speedup vs baseline: 1.3662x; 1.3662x over previous
#include <cuda_runtime.h>
#include <cstdint>

#define NSTEPS 64
#define DD 16
#define THREADS 352
#define RPT 4
#define ROWS_PER_CTA (THREADS * RPT)          // 1408
#define WEIGHT_FLOATS (NSTEPS * DD * DD)
#define SMEM_BYTES (2 * WEIGHT_FLOATS * 4)    // 128 KB: W then V/64

typedef unsigned long long u64;

// ---- packed f32x2 helpers (sm_103a) ----
__device__ __forceinline__ u64 pack2(float lo, float hi) {
    u64 r;
    asm("mov.b64 %0, {%1, %2};" : "=l"(r) : "f"(lo), "f"(hi));
    return r;
}
__device__ __forceinline__ void unpack2(u64 v, float& lo, float& hi) {
    asm("mov.b64 {%0, %1}, %2;" : "=f"(lo), "=f"(hi) : "l"(v));
}
__device__ __forceinline__ u64 fma2(u64 a, u64 b, u64 c) {
    u64 d;
    asm("fma.rn.f32x2 %0, %1, %2, %3;" : "=l"(d) : "l"(a), "l"(b), "l"(c));
    return d;
}
__device__ __forceinline__ u64 mul2(u64 a, u64 b) {
    u64 d;
    asm("mul.rn.f32x2 %0, %1, %2;" : "=l"(d) : "l"(a), "l"(b));
    return d;
}
__device__ __forceinline__ float rcp_fast(float x) {
    float r;
    asm("rcp.approx.ftz.f32 %0, %1;" : "=f"(r) : "f"(x));
    return r;
}
__device__ __forceinline__ float ex2_fast(float x) {
    float r;
    asm("ex2.approx.ftz.f32 %0, %1;" : "=f"(r) : "f"(x));
    return r;
}

// A&S 7.1.26 erf constants
#define ERF_P   0.3275911f
#define ERF_A1  0.254829592f
#define ERF_A2 -0.284496736f
#define ERF_A3  1.421413741f
#define ERF_A4 -1.453152027f
#define ERF_A5  1.061405429f
#define INV_SQRT2 0.70710678118654752440f
#define NEG_LOG2E -1.44269504088896340736f

// gelu on a packed pair: returns (gelu(x), gelu(y)); erf via A&S 7.1.26
__device__ __forceinline__ u64 gelu2(u64 xy) {
    float x, y;
    unpack2(xy, x, y);
    float ax = fabsf(x) * INV_SQRT2;
    float ay = fabsf(y) * INV_SQRT2;
    float tx = rcp_fast(fmaf(ERF_P, ax, 1.0f));
    float ty = rcp_fast(fmaf(ERF_P, ay, 1.0f));
    float ex = ex2_fast(ax * ax * NEG_LOG2E);
    float ey = ex2_fast(ay * ay * NEG_LOG2E);
    u64 t2 = pack2(tx, ty);
    u64 e2 = pack2(ex, ey);
    u64 p = fma2(pack2(-ERF_A5, -ERF_A5), t2, pack2(-ERF_A4, -ERF_A4));
    p = fma2(p, t2, pack2(-ERF_A3, -ERF_A3));
    p = fma2(p, t2, pack2(-ERF_A2, -ERF_A2));
    p = fma2(p, t2, pack2(-ERF_A1, -ERF_A1));
    p = mul2(p, t2);
    u64 E2 = fma2(p, e2, pack2(1.0f, 1.0f));               // E = 1 - P(t)*e^{-z^2}
    u64 half2 = pack2(0.5f, 0.5f);
    u64 habs = mul2(xy & 0x7fffffff7fffffffULL, half2);     // 0.5*|x|
    u64 hx = mul2(xy, half2);                               // 0.5*x
    return fma2(habs, E2, hx);                              // 0.5x + 0.5|x|*E
}

__global__ __launch_bounds__(THREADS)
void resnet_steps_kernel(const float* __restrict__ x,
                         const float* __restrict__ W,
                         const float* __restrict__ V,
                         float* __restrict__ out,
                         long long batch)
{
    extern __shared__ float smem[];   // [0,16384): W ; [16384,32768): V * (1/64)
    const int tid = threadIdx.x;

    {
        const float4* Wg = reinterpret_cast<const float4*>(W);
        const float4* Vg = reinterpret_cast<const float4*>(V);
        float4* sW4 = reinterpret_cast<float4*>(smem);
        float4* sV4 = reinterpret_cast<float4*>(smem + WEIGHT_FLOATS);
        const float invn = 1.0f / (float)NSTEPS;
        for (int i = tid; i < WEIGHT_FLOATS / 4; i += THREADS) {
            sW4[i] = Wg[i];
            float4 v = Vg[i];
            v.x *= invn; v.y *= invn; v.z *= invn; v.w *= invn;
            sV4[i] = v;
        }
    }
    __syncthreads();

    const long long base_row = (long long)blockIdx.x * ROWS_PER_CTA + tid;

    u64 h[RPT][8];
    #pragma unroll
    for (int r = 0; r < RPT; r++) {
        const long long row = base_row + (long long)r * THREADS;
        if (row < batch) {
            const float4* xr = reinterpret_cast<const float4*>(x + row * DD);
            #pragma unroll
            for (int q = 0; q < 4; q++) {
                float4 t = xr[q];
                h[r][2 * q]     = pack2(t.x, t.y);
                h[r][2 * q + 1] = pack2(t.z, t.w);
            }
        } else {
            #pragma unroll
            for (int i = 0; i < 8; i++) h[r][i] = 0ULL;
        }
    }

    const ulonglong2* sW = reinterpret_cast<const ulonglong2*>(smem);
    const ulonglong2* sV = reinterpret_cast<const ulonglong2*>(smem + WEIGHT_FLOATS);

    #pragma unroll 1
    for (int s = 0; s < NSTEPS; s++) {
        const ulonglong2* Ws = sW + s * (DD * DD / 4);
        const ulonglong2* Vs = sV + s * (DD * DD / 4);

        // ---- g = h @ W_s ----
        u64 acc[RPT][8];
        #pragma unroll
        for (int r = 0; r < RPT; r++)
            #pragma unroll
            for (int i = 0; i < 8; i++) acc[r][i] = 0ULL;

        #pragma unroll 1
        for (int kp = 0; kp < 8; kp++) {
            ulonglong2 w0 = Ws[kp * 8 + 0];
            ulonglong2 w1 = Ws[kp * 8 + 1];
            ulonglong2 w2 = Ws[kp * 8 + 2];
            ulonglong2 w3 = Ws[kp * 8 + 3];
            ulonglong2 w4 = Ws[kp * 8 + 4];
            ulonglong2 w5 = Ws[kp * 8 + 5];
            ulonglong2 w6 = Ws[kp * 8 + 6];
            ulonglong2 w7 = Ws[kp * 8 + 7];
            #pragma unroll
            for (int r = 0; r < RPT; r++) {
                float a, b;
                unpack2(h[r][kp], a, b);
                const u64 ha = pack2(a, a);
                const u64 hb = pack2(b, b);
                acc[r][0] = fma2(ha, w0.x, acc[r][0]);
                acc[r][1] = fma2(ha, w0.y, acc[r][1]);
                acc[r][2] = fma2(ha, w1.x, acc[r][2]);
                acc[r][3] = fma2(ha, w1.y, acc[r][3]);
                acc[r][4] = fma2(ha, w2.x, acc[r][4]);
                acc[r][5] = fma2(ha, w2.y, acc[r][5]);
                acc[r][6] = fma2(ha, w3.x, acc[r][6]);
                acc[r][7] = fma2(ha, w3.y, acc[r][7]);
                acc[r][0] = fma2(hb, w4.x, acc[r][0]);
                acc[r][1] = fma2(hb, w4.y, acc[r][1]);
                acc[r][2] = fma2(hb, w5.x, acc[r][2]);
                acc[r][3] = fma2(hb, w5.y, acc[r][3]);
                acc[r][4] = fma2(hb, w6.x, acc[r][4]);
                acc[r][5] = fma2(hb, w6.y, acc[r][5]);
                acc[r][6] = fma2(hb, w7.x, acc[r][6]);
                acc[r][7] = fma2(hb, w7.y, acc[r][7]);
            }
        }

        // ---- h += GELU(g) @ (V_s/64); fast packed A&S erf ----
        #pragma unroll 1
        for (int kp = 0; kp < 8; kp++) {
            ulonglong2 v0 = Vs[kp * 8 + 0];
            ulonglong2 v1 = Vs[kp * 8 + 1];
            ulonglong2 v2 = Vs[kp * 8 + 2];
            ulonglong2 v3 = Vs[kp * 8 + 3];
            ulonglong2 v4 = Vs[kp * 8 + 4];
            ulonglong2 v5 = Vs[kp * 8 + 5];
            ulonglong2 v6 = Vs[kp * 8 + 6];
            ulonglong2 v7 = Vs[kp * 8 + 7];
            #pragma unroll
            for (int r = 0; r < RPT; r++) {
                u64 g2 = gelu2(acc[r][kp]);
                float a, b;
                unpack2(g2, a, b);
                const u64 ga = pack2(a, a);
                const u64 gb = pack2(b, b);
                h[r][0] = fma2(ga, v0.x, h[r][0]);
                h[r][1] = fma2(ga, v0.y, h[r][1]);
                h[r][2] = fma2(ga, v1.x, h[r][2]);
                h[r][3] = fma2(ga, v1.y, h[r][3]);
                h[r][4] = fma2(ga, v2.x, h[r][4]);
                h[r][5] = fma2(ga, v2.y, h[r][5]);
                h[r][6] = fma2(ga, v3.x, h[r][6]);
                h[r][7] = fma2(ga, v3.y, h[r][7]);
                h[r][0] = fma2(gb, v4.x, h[r][0]);
                h[r][1] = fma2(gb, v4.y, h[r][1]);
                h[r][2] = fma2(gb, v5.x, h[r][2]);
                h[r][3] = fma2(gb, v5.y, h[r][3]);
                h[r][4] = fma2(gb, v6.x, h[r][4]);
                h[r][5] = fma2(gb, v6.y, h[r][5]);
                h[r][6] = fma2(gb, v7.x, h[r][6]);
                h[r][7] = fma2(gb, v7.y, h[r][7]);
            }
        }
    }

    #pragma unroll
    for (int r = 0; r < RPT; r++) {
        const long long row = base_row + (long long)r * THREADS;
        if (row < batch) {
            float4* orow = reinterpret_cast<float4*>(out + row * DD);
            #pragma unroll
            for (int q = 0; q < 4; q++) {
                float4 t;
                unpack2(h[r][2 * q],     t.x, t.y);
                unpack2(h[r][2 * q + 1], t.z, t.w);
                orow[q] = t;
            }
        }
    }
}

extern "C" void kernel_launch(void* const* d_in, const int* in_sizes, int n_in,
                              void* d_out, int out_size) {
    const float* x = (const float*)d_in[0];
    const float* W = (const float*)d_in[1];
    const float* V = (const float*)d_in[2];
    float* out = (float*)d_out;

    static bool attr_set = false;
    if (!attr_set) {
        cudaFuncSetAttribute(resnet_steps_kernel,
                             cudaFuncAttributeMaxDynamicSharedMemorySize, SMEM_BYTES);
        attr_set = true;
    }

    const long long batch = (long long)in_sizes[0] / DD;   // 2^21
    const int grid = (int)((batch + ROWS_PER_CTA - 1) / ROWS_PER_CTA);
    resnet_steps_kernel<<<grid, THREADS, SMEM_BYTES>>>(x, W, V, out, batch);
}

// round 7
// speedup vs baseline: 1.5887x; 1.1628x over previous
#include <cuda_runtime.h>
#include <cstdint>

#define NSTEPS 64
#define DD 16
#define THREADS 512
#define RPT 2
#define ROWS_PER_CTA (THREADS * RPT)            // 1024 (divides 2^21 exactly)
#define WEIGHT_VALS (NSTEPS * DD * DD)          // 16384 per tensor
#define WEIGHT_U32 (WEIGHT_VALS / 2)            // 8192 u32 (bf16 pairs)
#define SMEM_BYTES (2 * WEIGHT_U32 * 4)         // 64 KB: W_bf16 then (V/64)_bf16

typedef unsigned long long u64;
typedef unsigned int u32;

// ---- packed f32x2 helpers (sm_103a) ----
__device__ __forceinline__ u64 pack2(float lo, float hi) {
    u64 r;
    asm("mov.b64 %0, {%1, %2};" : "=l"(r) : "f"(lo), "f"(hi));
    return r;
}
__device__ __forceinline__ void unpack2(u64 v, float& lo, float& hi) {
    asm("mov.b64 {%0, %1}, %2;" : "=f"(lo), "=f"(hi) : "l"(v));
}
__device__ __forceinline__ u64 fma2(u64 a, u64 b, u64 c) {
    u64 d;
    asm("fma.rn.f32x2 %0, %1, %2, %3;" : "=l"(d) : "l"(a), "l"(b), "l"(c));
    return d;
}
__device__ __forceinline__ u64 mul2(u64 a, u64 b) {
    u64 d;
    asm("mul.rn.f32x2 %0, %1, %2;" : "=l"(d) : "l"(a), "l"(b));
    return d;
}
__device__ __forceinline__ float rcp_fast(float x) {
    float r;
    asm("rcp.approx.ftz.f32 %0, %1;" : "=f"(r) : "f"(x));
    return r;
}
__device__ __forceinline__ float ex2_fast(float x) {
    float r;
    asm("ex2.approx.ftz.f32 %0, %1;" : "=f"(r) : "f"(x));
    return r;
}

// bf16 pair (packed in one u32, lo half = element j, hi half = element j+1)
// expanded to packed f32x2. fp32 = bf16 << 16. 2 alu ops + reg-pair mov.
__device__ __forceinline__ u64 bfpair(u32 w) {
    u32 lo = w << 16;
    u32 hi = w & 0xffff0000u;
    u64 r;
    asm("mov.b64 %0, {%1, %2};" : "=l"(r) : "r"(lo), "r"(hi));
    return r;
}

// fp32 pair -> bf16x2 (round-to-nearest), for the smem fill.
__device__ __forceinline__ u32 to_bf16x2(float lo, float hi) {
    u32 r;
    asm("cvt.rn.bf16x2.f32 %0, %1, %2;" : "=r"(r) : "f"(hi), "f"(lo));
    return r;
}

// A&S 7.1.26 erf constants
#define ERF_P   0.3275911f
#define ERF_A1  0.254829592f
#define ERF_A2 -0.284496736f
#define ERF_A3  1.421413741f
#define ERF_A4 -1.453152027f
#define ERF_A5  1.061405429f
#define INV_SQRT2 0.70710678118654752440f
#define NEG_LOG2E -1.44269504088896340736f
#define ABS2_MASK 0x7fffffff7fffffffULL

// gelu on a packed pair; erf via A&S 7.1.26, argument prep packed.
__device__ __forceinline__ u64 gelu2(u64 xy) {
    const u64 isq2  = pack2(INV_SQRT2, INV_SQRT2);
    const u64 one2  = pack2(1.0f, 1.0f);
    const u64 half2 = pack2(0.5f, 0.5f);
    const u64 nl2e  = pack2(NEG_LOG2E, NEG_LOG2E);
    const u64 p2    = pack2(ERF_P, ERF_P);

    u64 axy = xy & ABS2_MASK;                 // |x|, |y|
    u64 z2  = mul2(axy, isq2);                // z = |x|/sqrt(2)
    u64 tin = fma2(p2, z2, one2);             // 1 + p*z
    u64 zz  = mul2(z2, z2);
    u64 ea  = mul2(zz, nl2e);                 // -log2(e)*z^2
    float ti_l, ti_h, ea_l, ea_h;
    unpack2(tin, ti_l, ti_h);
    unpack2(ea, ea_l, ea_h);
    u64 t2 = pack2(rcp_fast(ti_l), rcp_fast(ti_h));
    u64 e2 = pack2(ex2_fast(ea_l), ex2_fast(ea_h));
    // P = -(a5 t^5 + ... + a1 t) via negated coefs (packed Horner)
    u64 p = fma2(pack2(-ERF_A5, -ERF_A5), t2, pack2(-ERF_A4, -ERF_A4));
    p = fma2(p, t2, pack2(-ERF_A3, -ERF_A3));
    p = fma2(p, t2, pack2(-ERF_A2, -ERF_A2));
    p = fma2(p, t2, pack2(-ERF_A1, -ERF_A1));
    p = mul2(p, t2);
    u64 E2 = fma2(p, e2, one2);               // E = 1 - P(t)*e^{-z^2}
    u64 hx   = mul2(xy, half2);               // 0.5*x
    u64 habs = hx & ABS2_MASK;                // 0.5*|x|
    return fma2(habs, E2, hx);                // 0.5x + 0.5|x|*E
}

__global__ __launch_bounds__(THREADS)
void resnet_steps_kernel(const float* __restrict__ x,
                         const float* __restrict__ W,
                         const float* __restrict__ V,
                         float* __restrict__ out)
{
    extern __shared__ u32 smem[];   // [0,8192): W bf16x2 ; [8192,16384): (V/64) bf16x2
    const int tid = threadIdx.x;

    // Cooperative fill: fp32 global -> bf16x2 smem. V pre-scaled by 1/64.
    {
        const float2* Wg = reinterpret_cast<const float2*>(W);
        const float2* Vg = reinterpret_cast<const float2*>(V);
        const float invn = 1.0f / (float)NSTEPS;
        for (int i = tid; i < WEIGHT_U32; i += THREADS) {
            float2 w = Wg[i];
            smem[i] = to_bf16x2(w.x, w.y);
            float2 v = Vg[i];
            smem[WEIGHT_U32 + i] = to_bf16x2(v.x * invn, v.y * invn);
        }
    }
    __syncthreads();

    const int base_row = blockIdx.x * ROWS_PER_CTA + tid;   // fits in int

    u64 h[RPT][8];
    #pragma unroll
    for (int r = 0; r < RPT; r++) {
        const float4* xr = reinterpret_cast<const float4*>(x) + (base_row + r * THREADS) * 4;
        #pragma unroll
        for (int q = 0; q < 4; q++) {
            float4 t = xr[q];
            h[r][2 * q]     = pack2(t.x, t.y);
            h[r][2 * q + 1] = pack2(t.z, t.w);
        }
    }

    const uint4* sW = reinterpret_cast<const uint4*>(smem);                 // 2 uint4 per W row
    const uint4* sV = reinterpret_cast<const uint4*>(smem + WEIGHT_U32);

    #pragma unroll 1
    for (int s = 0; s < NSTEPS; s++) {
        const uint4* Ws = sW + s * (DD * DD / 8);   // 32 uint4 per step
        const uint4* Vs = sV + s * (DD * DD / 8);

        // ---- g = h @ W_s ----
        u64 acc[RPT][8];
        #pragma unroll
        for (int r = 0; r < RPT; r++)
            #pragma unroll
            for (int i = 0; i < 8; i++) acc[r][i] = 0ULL;

        #pragma unroll 1
        for (int kp = 0; kp < 8; kp++) {
            // W row 2kp: 16 bf16 = 2 LDS.128 -> 8 packed multiplicands
            {
                uint4 wa = Ws[kp * 4 + 0];
                uint4 wb = Ws[kp * 4 + 1];
                u64 m0 = bfpair(wa.x), m1 = bfpair(wa.y), m2 = bfpair(wa.z), m3 = bfpair(wa.w);
                u64 m4 = bfpair(wb.x), m5 = bfpair(wb.y), m6 = bfpair(wb.z), m7 = bfpair(wb.w);
                #pragma unroll
                for (int r = 0; r < RPT; r++) {
                    float a, b;
                    unpack2(h[r][kp], a, b);
                    (void)b;
                    const u64 ha = pack2(a, a);
                    acc[r][0] = fma2(ha, m0, acc[r][0]);
                    acc[r][1] = fma2(ha, m1, acc[r][1]);
                    acc[r][2] = fma2(ha, m2, acc[r][2]);
                    acc[r][3] = fma2(ha, m3, acc[r][3]);
                    acc[r][4] = fma2(ha, m4, acc[r][4]);
                    acc[r][5] = fma2(ha, m5, acc[r][5]);
                    acc[r][6] = fma2(ha, m6, acc[r][6]);
                    acc[r][7] = fma2(ha, m7, acc[r][7]);
                }
            }
            // W row 2kp+1
            {
                uint4 wc = Ws[kp * 4 + 2];
                uint4 wd = Ws[kp * 4 + 3];
                u64 m0 = bfpair(wc.x), m1 = bfpair(wc.y), m2 = bfpair(wc.z), m3 = bfpair(wc.w);
                u64 m4 = bfpair(wd.x), m5 = bfpair(wd.y), m6 = bfpair(wd.z), m7 = bfpair(wd.w);
                #pragma unroll
                for (int r = 0; r < RPT; r++) {
                    float a, b;
                    unpack2(h[r][kp], a, b);
                    (void)a;
                    const u64 hb = pack2(b, b);
                    acc[r][0] = fma2(hb, m0, acc[r][0]);
                    acc[r][1] = fma2(hb, m1, acc[r][1]);
                    acc[r][2] = fma2(hb, m2, acc[r][2]);
                    acc[r][3] = fma2(hb, m3, acc[r][3]);
                    acc[r][4] = fma2(hb, m4, acc[r][4]);
                    acc[r][5] = fma2(hb, m5, acc[r][5]);
                    acc[r][6] = fma2(hb, m6, acc[r][6]);
                    acc[r][7] = fma2(hb, m7, acc[r][7]);
                }
            }
        }

        // ---- h += GELU(g) @ (V_s/64) ----
        #pragma unroll 1
        for (int kp = 0; kp < 8; kp++) {
            u64 g2[RPT];
            #pragma unroll
            for (int r = 0; r < RPT; r++) g2[r] = gelu2(acc[r][kp]);
            {
                uint4 va = Vs[kp * 4 + 0];
                uint4 vb = Vs[kp * 4 + 1];
                u64 m0 = bfpair(va.x), m1 = bfpair(va.y), m2 = bfpair(va.z), m3 = bfpair(va.w);
                u64 m4 = bfpair(vb.x), m5 = bfpair(vb.y), m6 = bfpair(vb.z), m7 = bfpair(vb.w);
                #pragma unroll
                for (int r = 0; r < RPT; r++) {
                    float a, b;
                    unpack2(g2[r], a, b);
                    (void)b;
                    const u64 ga = pack2(a, a);
                    h[r][0] = fma2(ga, m0, h[r][0]);
                    h[r][1] = fma2(ga, m1, h[r][1]);
                    h[r][2] = fma2(ga, m2, h[r][2]);
                    h[r][3] = fma2(ga, m3, h[r][3]);
                    h[r][4] = fma2(ga, m4, h[r][4]);
                    h[r][5] = fma2(ga, m5, h[r][5]);
                    h[r][6] = fma2(ga, m6, h[r][6]);
                    h[r][7] = fma2(ga, m7, h[r][7]);
                }
            }
            {
                uint4 vc = Vs[kp * 4 + 2];
                uint4 vd = Vs[kp * 4 + 3];
                u64 m0 = bfpair(vc.x), m1 = bfpair(vc.y), m2 = bfpair(vc.z), m3 = bfpair(vc.w);
                u64 m4 = bfpair(vd.x), m5 = bfpair(vd.y), m6 = bfpair(vd.z), m7 = bfpair(vd.w);
                #pragma unroll
                for (int r = 0; r < RPT; r++) {
                    float a, b;
                    unpack2(g2[r], a, b);
                    (void)a;
                    const u64 gb = pack2(b, b);
                    h[r][0] = fma2(gb, m0, h[r][0]);
                    h[r][1] = fma2(gb, m1, h[r][1]);
                    h[r][2] = fma2(gb, m2, h[r][2]);
                    h[r][3] = fma2(gb, m3, h[r][3]);
                    h[r][4] = fma2(gb, m4, h[r][4]);
                    h[r][5] = fma2(gb, m5, h[r][5]);
                    h[r][6] = fma2(gb, m6, h[r][6]);
                    h[r][7] = fma2(gb, m7, h[r][7]);
                }
            }
        }
    }

    #pragma unroll
    for (int r = 0; r < RPT; r++) {
        float4* orow = reinterpret_cast<float4*>(out) + (base_row + r * THREADS) * 4;
        #pragma unroll
        for (int q = 0; q < 4; q++) {
            float4 t;
            unpack2(h[r][2 * q],     t.x, t.y);
            unpack2(h[r][2 * q + 1], t.z, t.w);
            orow[q] = t;
        }
    }
}

extern "C" void kernel_launch(void* const* d_in, const int* in_sizes, int n_in,
                              void* d_out, int out_size) {
    const float* x = (const float*)d_in[0];
    const float* W = (const float*)d_in[1];
    const float* V = (const float*)d_in[2];
    float* out = (float*)d_out;

    static bool attr_set = false;
    if (!attr_set) {
        cudaFuncSetAttribute(resnet_steps_kernel,
                             cudaFuncAttributeMaxDynamicSharedMemorySize, SMEM_BYTES);
        attr_set = true;
    }

    const long long batch = (long long)in_sizes[0] / DD;   // 2^21
    const int grid = (int)(batch / ROWS_PER_CTA);          // 2048, exact
    resnet_steps_kernel<<<grid, THREADS, SMEM_BYTES>>>(x, W, V, out);
}

// round 8
// speedup vs baseline: 2.0983x; 1.3208x over previous
#include <cuda_runtime.h>
#include <cstdint>

#define NSTEPS 64
#define DD 16
#define THREADS 256
#define RPT 2
#define ROWS_PER_CTA (THREADS * RPT)            // 512 (divides 2^21 exactly)
#define WEIGHT_FLOATS (NSTEPS * DD * DD)        // 16384
#define SMEM_BYTES (WEIGHT_FLOATS * 4)          // 64 KB: W only

typedef unsigned long long u64;

// V lives in constant memory (64 KB), filled per-call with cudaMemcpyToSymbolAsync.
__constant__ float cV[WEIGHT_FLOATS];

// ---- packed f32x2 helpers (sm_103a) ----
__device__ __forceinline__ u64 pack2(float lo, float hi) {
    u64 r;
    asm("mov.b64 %0, {%1, %2};" : "=l"(r) : "f"(lo), "f"(hi));
    return r;
}
__device__ __forceinline__ void unpack2(u64 v, float& lo, float& hi) {
    asm("mov.b64 {%0, %1}, %2;" : "=f"(lo), "=f"(hi) : "l"(v));
}
__device__ __forceinline__ u64 fma2(u64 a, u64 b, u64 c) {
    u64 d;
    asm("fma.rn.f32x2 %0, %1, %2, %3;" : "=l"(d) : "l"(a), "l"(b), "l"(c));
    return d;
}
__device__ __forceinline__ u64 mul2(u64 a, u64 b) {
    u64 d;
    asm("mul.rn.f32x2 %0, %1, %2;" : "=l"(d) : "l"(a), "l"(b));
    return d;
}
__device__ __forceinline__ float rcp_fast(float x) {
    float r;
    asm("rcp.approx.ftz.f32 %0, %1;" : "=f"(r) : "f"(x));
    return r;
}
__device__ __forceinline__ float ex2_fast(float x) {
    float r;
    asm("ex2.approx.ftz.f32 %0, %1;" : "=f"(r) : "f"(x));
    return r;
}

// A&S 7.1.26 erf constants
#define ERF_P   0.3275911f
#define ERF_A1  0.254829592f
#define ERF_A2 -0.284496736f
#define ERF_A3  1.421413741f
#define ERF_A4 -1.453152027f
#define ERF_A5  1.061405429f
#define INV_SQRT2 0.70710678118654752440f
#define NEG_LOG2E -1.44269504088896340736f
#define ABS2_MASK 0x7fffffff7fffffffULL
// 0.5/64: folds the residual 1/NSTEPS scaling into GELU for free
#define HALF_INVN (0.5f / 64.0f)

// returns (gelu(x)/64, gelu(y)/64); erf via A&S 7.1.26
__device__ __forceinline__ u64 gelu2_scaled(u64 xy) {
    float x, y;
    unpack2(xy, x, y);
    float ax = fabsf(x) * INV_SQRT2;
    float ay = fabsf(y) * INV_SQRT2;
    float tx = rcp_fast(fmaf(ERF_P, ax, 1.0f));
    float ty = rcp_fast(fmaf(ERF_P, ay, 1.0f));
    float ex = ex2_fast(ax * ax * NEG_LOG2E);
    float ey = ex2_fast(ay * ay * NEG_LOG2E);
    u64 t2 = pack2(tx, ty);
    u64 e2 = pack2(ex, ey);
    u64 p = fma2(pack2(-ERF_A5, -ERF_A5), t2, pack2(-ERF_A4, -ERF_A4));
    p = fma2(p, t2, pack2(-ERF_A3, -ERF_A3));
    p = fma2(p, t2, pack2(-ERF_A2, -ERF_A2));
    p = fma2(p, t2, pack2(-ERF_A1, -ERF_A1));
    p = mul2(p, t2);
    u64 E2 = fma2(p, e2, pack2(1.0f, 1.0f));            // E = 1 - P(t)*e^{-z^2}
    u64 sc2 = pack2(HALF_INVN, HALF_INVN);
    u64 hx   = mul2(xy, sc2);                           // (0.5/64)*x
    u64 habs = hx & ABS2_MASK;                          // (0.5/64)*|x|
    return fma2(habs, E2, hx);                          // (x/2 + |x|/2*E)/64
}

__global__ __launch_bounds__(THREADS, 2)
void resnet_steps_kernel(const float* __restrict__ x,
                         const float* __restrict__ W,
                         float* __restrict__ out)
{
    extern __shared__ float smem[];   // [0,16384): W fp32
    const int tid = threadIdx.x;

    {
        const float4* Wg = reinterpret_cast<const float4*>(W);
        float4* sW4 = reinterpret_cast<float4*>(smem);
        for (int i = tid; i < WEIGHT_FLOATS / 4; i += THREADS)
            sW4[i] = Wg[i];
    }
    __syncthreads();

    const int base_row = blockIdx.x * ROWS_PER_CTA + tid;

    u64 h[RPT][8];
    #pragma unroll
    for (int r = 0; r < RPT; r++) {
        const float4* xr = reinterpret_cast<const float4*>(x) + (base_row + r * THREADS) * 4;
        #pragma unroll
        for (int q = 0; q < 4; q++) {
            float4 t = xr[q];
            h[r][2 * q]     = pack2(t.x, t.y);
            h[r][2 * q + 1] = pack2(t.z, t.w);
        }
    }

    const ulonglong2* sW = reinterpret_cast<const ulonglong2*>(smem);
    const ulonglong2* cVp = reinterpret_cast<const ulonglong2*>(cV);

    #pragma unroll 1
    for (int s = 0; s < NSTEPS; s++) {
        const ulonglong2* Ws = sW + s * (DD * DD / 4);    // 64 ulonglong2 per step
        const ulonglong2* Vs = cVp + s * (DD * DD / 4);

        // ---- g = h @ W_s  (W from shared memory, LDS.128 broadcast) ----
        u64 acc[RPT][8];
        #pragma unroll
        for (int r = 0; r < RPT; r++)
            #pragma unroll
            for (int i = 0; i < 8; i++) acc[r][i] = 0ULL;

        #pragma unroll 1
        for (int kp = 0; kp < 8; kp++) {
            ulonglong2 w0 = Ws[kp * 8 + 0];
            ulonglong2 w1 = Ws[kp * 8 + 1];
            ulonglong2 w2 = Ws[kp * 8 + 2];
            ulonglong2 w3 = Ws[kp * 8 + 3];
            ulonglong2 w4 = Ws[kp * 8 + 4];
            ulonglong2 w5 = Ws[kp * 8 + 5];
            ulonglong2 w6 = Ws[kp * 8 + 6];
            ulonglong2 w7 = Ws[kp * 8 + 7];
            #pragma unroll
            for (int r = 0; r < RPT; r++) {
                float a, b;
                unpack2(h[r][kp], a, b);
                const u64 ha = pack2(a, a);
                const u64 hb = pack2(b, b);
                acc[r][0] = fma2(ha, w0.x, acc[r][0]);
                acc[r][1] = fma2(ha, w0.y, acc[r][1]);
                acc[r][2] = fma2(ha, w1.x, acc[r][2]);
                acc[r][3] = fma2(ha, w1.y, acc[r][3]);
                acc[r][4] = fma2(ha, w2.x, acc[r][4]);
                acc[r][5] = fma2(ha, w2.y, acc[r][5]);
                acc[r][6] = fma2(ha, w3.x, acc[r][6]);
                acc[r][7] = fma2(ha, w3.y, acc[r][7]);
                acc[r][0] = fma2(hb, w4.x, acc[r][0]);
                acc[r][1] = fma2(hb, w4.y, acc[r][1]);
                acc[r][2] = fma2(hb, w5.x, acc[r][2]);
                acc[r][3] = fma2(hb, w5.y, acc[r][3]);
                acc[r][4] = fma2(hb, w6.x, acc[r][4]);
                acc[r][5] = fma2(hb, w6.y, acc[r][5]);
                acc[r][6] = fma2(hb, w7.x, acc[r][6]);
                acc[r][7] = fma2(hb, w7.y, acc[r][7]);
            }
        }

        // ---- h += (GELU(g)/64) @ V_s  (V from constant memory, LDC.128) ----
        #pragma unroll 1
        for (int kp = 0; kp < 8; kp++) {
            ulonglong2 v0 = Vs[kp * 8 + 0];
            ulonglong2 v1 = Vs[kp * 8 + 1];
            ulonglong2 v2 = Vs[kp * 8 + 2];
            ulonglong2 v3 = Vs[kp * 8 + 3];
            ulonglong2 v4 = Vs[kp * 8 + 4];
            ulonglong2 v5 = Vs[kp * 8 + 5];
            ulonglong2 v6 = Vs[kp * 8 + 6];
            ulonglong2 v7 = Vs[kp * 8 + 7];
            #pragma unroll
            for (int r = 0; r < RPT; r++) {
                u64 g2 = gelu2_scaled(acc[r][kp]);
                float a, b;
                unpack2(g2, a, b);
                const u64 ga = pack2(a, a);
                const u64 gb = pack2(b, b);
                h[r][0] = fma2(ga, v0.x, h[r][0]);
                h[r][1] = fma2(ga, v0.y, h[r][1]);
                h[r][2] = fma2(ga, v1.x, h[r][2]);
                h[r][3] = fma2(ga, v1.y, h[r][3]);
                h[r][4] = fma2(ga, v2.x, h[r][4]);
                h[r][5] = fma2(ga, v2.y, h[r][5]);
                h[r][6] = fma2(ga, v3.x, h[r][6]);
                h[r][7] = fma2(ga, v3.y, h[r][7]);
                h[r][0] = fma2(gb, v4.x, h[r][0]);
                h[r][1] = fma2(gb, v4.y, h[r][1]);
                h[r][2] = fma2(gb, v5.x, h[r][2]);
                h[r][3] = fma2(gb, v5.y, h[r][3]);
                h[r][4] = fma2(gb, v6.x, h[r][4]);
                h[r][5] = fma2(gb, v6.y, h[r][5]);
                h[r][6] = fma2(gb, v7.x, h[r][6]);
                h[r][7] = fma2(gb, v7.y, h[r][7]);
            }
        }
    }

    #pragma unroll
    for (int r = 0; r < RPT; r++) {
        float4* orow = reinterpret_cast<float4*>(out) + (base_row + r * THREADS) * 4;
        #pragma unroll
        for (int q = 0; q < 4; q++) {
            float4 t;
            unpack2(h[r][2 * q],     t.x, t.y);
            unpack2(h[r][2 * q + 1], t.z, t.w);
            orow[q] = t;
        }
    }
}

extern "C" void kernel_launch(void* const* d_in, const int* in_sizes, int n_in,
                              void* d_out, int out_size) {
    const float* x = (const float*)d_in[0];
    const float* W = (const float*)d_in[1];
    const float* V = (const float*)d_in[2];
    float* out = (float*)d_out;

    static bool attr_set = false;
    if (!attr_set) {
        cudaFuncSetAttribute(resnet_steps_kernel,
                             cudaFuncAttributeMaxDynamicSharedMemorySize, SMEM_BYTES);
        attr_set = true;
    }

    // V -> constant memory (device-to-device, graph-capturable memcpy node)
    cudaMemcpyToSymbolAsync(cV, V, WEIGHT_FLOATS * sizeof(float), 0,
                            cudaMemcpyDeviceToDevice);

    const long long batch = (long long)in_sizes[0] / DD;   // 2^21
    const int grid = (int)(batch / ROWS_PER_CTA);          // 4096, exact
    resnet_steps_kernel<<<grid, THREADS, SMEM_BYTES>>>(x, W, out);
}